// round 6
// baseline (speedup 1.0000x reference)
#include <cuda_runtime.h>

#define B_   32
#define T_   256
#define F_   64
#define C_   16
#define CO_  16
#define P_   64
#define S_   32
#define K_   4
#define FC   1024
#define KIN  1056
#define OUTC 96
#define ROWS (B_*T_)        // 8192
#define RSTR (F_*OUTC)      // 6144 floats per (b,t) row

// compact relu(point_out): 8192 x 64 fp32 = 2 MB (L2-resident)
__device__ __align__(256) float g_point[ROWS * P_];

// ---------------- packed f32x2 helpers ----------------
__device__ __forceinline__ double pack2(float lo, float hi) {
    double d; asm("mov.b64 %0, {%1, %2};" : "=d"(d) : "f"(lo), "f"(hi)); return d;
}
__device__ __forceinline__ float2 unpack2(double d) {
    float2 v; asm("mov.b64 {%0, %1}, %2;" : "=f"(v.x), "=f"(v.y) : "d"(d)); return v;
}
__device__ __forceinline__ void fma2(double& acc, double a, double b) {
    asm("fma.rn.f32x2 %0, %1, %2, %3;" : "=d"(acc) : "d"(a), "d"(b), "d"(acc));
}

// ============================================================================
// Kernel 1: point GEMM. grid=256, BM=32, BN=64, BK=32, reg-prefetch pipeline.
// ============================================================================
__global__ __launch_bounds__(256)
void tpc_gemm(const float* __restrict__ x,
              const float* __restrict__ stat,
              const float* __restrict__ W_p,
              const float* __restrict__ b_p)
{
    __shared__ __align__(16) float AsT[32][34];     // k-major A (pad 34 => 8B-aligned rows)
    __shared__ __align__(16) float Bsd[32][128];    // duplicated B

    const int tid  = threadIdx.x;
    const int row0 = blockIdx.x * 32;
    const int b    = row0 >> 8;
    const int m0   = (tid >> 4) * 2;      // m-pair
    const int n0   = (tid & 15) * 4;      // 4 n per thread

    // loader indices
    const int ar  = tid >> 3;             // 0..31
    const int akq = tid & 7;              // k-quad
    const int bkk = tid >> 4;             // 0..15
    const int bnq = tid & 15;

    double acc[4] = {0.0, 0.0, 0.0, 0.0};
    float4 pa, pb0, pb1;

    // prefetch kb = 0
    {
        pa  = *reinterpret_cast<const float4*>(&x[(size_t)(row0 + ar) * FC + akq * 4]);
        pb0 = *reinterpret_cast<const float4*>(&W_p[(size_t)bkk * P_ + bnq * 4]);
        pb1 = *reinterpret_cast<const float4*>(&W_p[(size_t)(bkk + 16) * P_ + bnq * 4]);
    }

    for (int kb = 0; kb < 33; ++kb) {
        // store prefetched tile to smem
        AsT[akq * 4 + 0][ar] = pa.x;
        AsT[akq * 4 + 1][ar] = pa.y;
        AsT[akq * 4 + 2][ar] = pa.z;
        AsT[akq * 4 + 3][ar] = pa.w;
        *reinterpret_cast<float4*>(&Bsd[bkk][bnq * 8])          = make_float4(pb0.x, pb0.x, pb0.y, pb0.y);
        *reinterpret_cast<float4*>(&Bsd[bkk][bnq * 8 + 4])      = make_float4(pb0.z, pb0.z, pb0.w, pb0.w);
        *reinterpret_cast<float4*>(&Bsd[bkk + 16][bnq * 8])     = make_float4(pb1.x, pb1.x, pb1.y, pb1.y);
        *reinterpret_cast<float4*>(&Bsd[bkk + 16][bnq * 8 + 4]) = make_float4(pb1.z, pb1.z, pb1.w, pb1.w);
        __syncthreads();

        // prefetch next tile (LDG in flight during compute)
        if (kb < 32) {
            int kg0 = (kb + 1) * 32;
            int kgf = kg0 + akq * 4;
            if (kgf < FC)
                pa = *reinterpret_cast<const float4*>(&x[(size_t)(row0 + ar) * FC + kgf]);
            else
                pa = *reinterpret_cast<const float4*>(&stat[b * S_ + (kgf - FC)]);
            pb0 = *reinterpret_cast<const float4*>(&W_p[(size_t)(kg0 + bkk) * P_ + bnq * 4]);
            pb1 = *reinterpret_cast<const float4*>(&W_p[(size_t)(kg0 + bkk + 16) * P_ + bnq * 4]);
        }

        #pragma unroll
        for (int kk = 0; kk < 32; ++kk) {
            double a    = *reinterpret_cast<const double*>(&AsT[kk][m0]);
            double2 b01 = *reinterpret_cast<const double2*>(&Bsd[kk][n0 * 2]);
            double2 b23 = *reinterpret_cast<const double2*>(&Bsd[kk][n0 * 2 + 4]);
            fma2(acc[0], a, b01.x);
            fma2(acc[1], a, b01.y);
            fma2(acc[2], a, b23.x);
            fma2(acc[3], a, b23.y);
        }
        __syncthreads();
    }

    // bias + relu -> g_point
    float4 bb = *reinterpret_cast<const float4*>(&b_p[n0]);
    float2 p0 = unpack2(acc[0]);
    float2 p1 = unpack2(acc[1]);
    float2 p2 = unpack2(acc[2]);
    float2 p3 = unpack2(acc[3]);
    float4 lo = make_float4(fmaxf(p0.x + bb.x, 0.f), fmaxf(p1.x + bb.y, 0.f),
                            fmaxf(p2.x + bb.z, 0.f), fmaxf(p3.x + bb.w, 0.f));
    float4 hi = make_float4(fmaxf(p0.y + bb.x, 0.f), fmaxf(p1.y + bb.y, 0.f),
                            fmaxf(p2.y + bb.z, 0.f), fmaxf(p3.y + bb.w, 0.f));
    int row = row0 + m0;
    *reinterpret_cast<float4*>(&g_point[(size_t)row * P_ + n0])       = lo;
    *reinterpret_cast<float4*>(&g_point[(size_t)(row + 1) * P_ + n0]) = hi;
}

// ============================================================================
// Kernel 2: interleaved roles. even blocks: conv (b,f) -> out ch16..31.
//           odd blocks: stream ch0..15 (relu x) + ch32..95 (g_point bcast).
// ============================================================================
__global__ __launch_bounds__(256)
void tpc_fuse(const float* __restrict__ x,
              const float* __restrict__ conv_w,
              const float* __restrict__ conv_b,
              float* __restrict__ out)
{
    __shared__ __align__(16) float xs[T_ + 6][17];  // 17.8 KB, conflict-free scalar reads
    __shared__ __align__(16) float ws[64][20];      // [c*4+k][co], LDS.128 = packed co-pairs
    __shared__ float bsv[16];

    const int tid = threadIdx.x;

    if ((blockIdx.x & 1) == 0) {
        // ---------------- CONV ROLE ----------------
        const int cb = blockIdx.x >> 1;
        const int b  = cb >> 6;
        const int f  = cb & 63;
        const size_t xrow0 = ((size_t)b * T_ * F_ + f) * C_;

        // x slab (rows 0..5 = zero pad; row r -> t = r-6)
        #pragma unroll
        for (int l = 0; l < 5; ++l) {
            int idx = tid + l * 256;
            if (idx < (T_ + 6) * 4) {
                int r = idx >> 2;
                int q = idx & 3;
                float4 v = make_float4(0.f, 0.f, 0.f, 0.f);
                if (r >= 6)
                    v = *reinterpret_cast<const float4*>(&x[xrow0 + (size_t)(r - 6) * FC + q * 4]);
                xs[r][q * 4 + 0] = v.x;
                xs[r][q * 4 + 1] = v.y;
                xs[r][q * 4 + 2] = v.z;
                xs[r][q * 4 + 3] = v.w;
            }
        }
        // weights transposed to [ck][co]
        {
            int co = tid >> 4;
            int c  = tid & 15;
            float4 w = *reinterpret_cast<const float4*>(&conv_w[((size_t)f * CO_ + co) * 64 + c * 4]);
            ws[c * 4 + 0][co] = w.x;
            ws[c * 4 + 1][co] = w.y;
            ws[c * 4 + 2][co] = w.z;
            ws[c * 4 + 3][co] = w.w;
        }
        if (tid < 16) bsv[tid] = conv_b[f * CO_ + tid];
        __syncthreads();

        const int t0  = (tid >> 2) * 4;
        const int co0 = (tid & 3) * 4;

        double acc[4][2];
        #pragma unroll
        for (int i = 0; i < 4; ++i) { acc[i][0] = 0.0; acc[i][1] = 0.0; }

        #pragma unroll 4
        for (int c = 0; c < C_; ++c) {
            double ad[10];
            #pragma unroll
            for (int r = 0; r < 10; ++r) {
                float a = xs[t0 + r][c];
                ad[r] = pack2(a, a);            // alu-pipe MOV, fma pipe untouched
            }
            #pragma unroll
            for (int k = 0; k < K_; ++k) {
                double2 w = *reinterpret_cast<const double2*>(&ws[c * 4 + k][co0]);
                #pragma unroll
                for (int i = 0; i < 4; ++i) {
                    fma2(acc[i][0], ad[i + 2 * k], w.x);
                    fma2(acc[i][1], ad[i + 2 * k], w.y);
                }
            }
        }

        // bias + relu, store ch16..31 straight from registers
        float4 bb = *reinterpret_cast<const float4*>(&bsv[co0]);
        float* ob = out + ((size_t)b * T_ * F_ + f) * OUTC;
        #pragma unroll
        for (int i = 0; i < 4; ++i) {
            float2 q0 = unpack2(acc[i][0]);
            float2 q1 = unpack2(acc[i][1]);
            float4 v = make_float4(fmaxf(q0.x + bb.x, 0.f), fmaxf(q0.y + bb.y, 0.f),
                                   fmaxf(q1.x + bb.z, 0.f), fmaxf(q1.y + bb.w, 0.f));
            *reinterpret_cast<float4*>(&ob[(size_t)(t0 + i) * RSTR + 16 + co0]) = v;
        }
    } else {
        // ---------------- STREAM ROLE ----------------
        const int rb = blockIdx.x >> 1;
        const int row_base = rb * 4;

        // ch 0..15: relu(x) (1024 float4)
        #pragma unroll
        for (int l = 0; l < 4; ++l) {
            int idx  = tid + l * 256;
            int r    = idx >> 8;
            int rest = idx & 255;            // f*4 + q
            int row  = row_base + r;
            float4 v = *reinterpret_cast<const float4*>(&x[(size_t)row * FC + rest * 4]);
            v.x = fmaxf(v.x, 0.f); v.y = fmaxf(v.y, 0.f);
            v.z = fmaxf(v.z, 0.f); v.w = fmaxf(v.w, 0.f);
            int f = rest >> 2;
            int q = rest & 3;
            *reinterpret_cast<float4*>(&out[(size_t)row * RSTR + f * OUTC + q * 4]) = v;
        }
        // ch 32..95: g_point broadcast (4096 float4)
        const int q  = tid & 15;
        const int f0 = tid >> 4;
        #pragma unroll
        for (int rr = 0; rr < 4; ++rr) {
            int row  = row_base + rr;
            float4 v = *reinterpret_cast<const float4*>(&g_point[(size_t)row * P_ + q * 4]);
            float* ob = out + (size_t)row * RSTR + 32 + q * 4;
            #pragma unroll
            for (int ff = 0; ff < 4; ++ff) {
                int f = ff * 16 + f0;
                *reinterpret_cast<float4*>(&ob[(size_t)f * OUTC]) = v;
            }
        }
    }
}

extern "C" void kernel_launch(void* const* d_in, const int* in_sizes, int n_in,
                              void* d_out, int out_size)
{
    const float* x      = (const float*)d_in[0];   // [32,256,64,16]
    const float* statv  = (const float*)d_in[1];   // [32,32]
    const float* conv_w = (const float*)d_in[2];   // [64,16,16,4]
    const float* conv_b = (const float*)d_in[3];   // [64,16]
    const float* W_p    = (const float*)d_in[4];   // [1056,64]
    const float* b_p    = (const float*)d_in[5];   // [64]
    float* out = (float*)d_out;                    // [32,256,64,96]

    tpc_gemm<<<ROWS / 32, 256>>>(x, statv, W_p, b_p);
    tpc_fuse<<<4096, 256>>>(x, conv_w, conv_b, out);
}

// round 7
// speedup vs baseline: 1.8325x; 1.8325x over previous
#include <cuda_runtime.h>

#define B_   32
#define T_   256
#define F_   64
#define C_   16
#define CO_  16
#define P_   64
#define S_   32
#define K_   4
#define FC   1024
#define KIN  1056
#define OUTC 96
#define ROWS (B_*T_)        // 8192
#define RSTR (F_*OUTC)      // 6144 floats per (b,t) row

// compact relu(point_out): 8192 x 64 fp32 = 2 MB (L2-resident)
__device__ __align__(256) float g_point[ROWS * P_];

// ---------------- packed f32x2 helpers ----------------
__device__ __forceinline__ double pack2(float lo, float hi) {
    double d; asm("mov.b64 %0, {%1, %2};" : "=d"(d) : "f"(lo), "f"(hi)); return d;
}
__device__ __forceinline__ float2 unpack2(double d) {
    float2 v; asm("mov.b64 {%0, %1}, %2;" : "=f"(v.x), "=f"(v.y) : "d"(d)); return v;
}
__device__ __forceinline__ void fma2(double& acc, double a, double b) {
    asm("fma.rn.f32x2 %0, %1, %2, %3;" : "=d"(acc) : "d"(a), "d"(b), "d"(acc));
}

// ============================================================================
// Kernel 1: point GEMM, pack-over-N. grid=256, BM=32, BN=64, BK=32.
// A duplicated (broadcast reads, conflict-free), B as natural float-pairs
// (conflict-free 8B-stride LDS.64). Micro-tile 2m x 4n = 4 FMA2 per kk.
// ============================================================================
__global__ __launch_bounds__(256)
void tpc_gemm(const float* __restrict__ x,
              const float* __restrict__ stat,
              const float* __restrict__ W_p,
              const float* __restrict__ b_p)
{
    __shared__ __align__(16) double Ad[32][33];   // [kk][m] dup doubles, 8.4 KB
    __shared__ __align__(16) float  Bsf[32][64];  // [kk][n] natural, 8 KB

    const int tid  = threadIdx.x;
    const int row0 = blockIdx.x * 32;
    const int b    = row0 >> 8;
    const int m0   = (tid >> 4) * 2;      // 2 m rows per thread
    const int ng   = tid & 15;            // n-pairs {ng, ng+16} -> n {2ng,2ng+1, 2ng+32,2ng+33}

    // loader indices
    const int ar  = tid >> 3;             // 0..31 (A row)
    const int akq = tid & 7;              // A k-quad
    const int bkk = tid >> 4;             // 0..15 (B kk, two halves)
    const int bnq = tid & 15;

    double acc0 = 0.0, acc1 = 0.0, acc2 = 0.0, acc3 = 0.0;
    float4 pa, pb0, pb1;

    // prefetch kb = 0
    pa  = *reinterpret_cast<const float4*>(&x[(size_t)(row0 + ar) * FC + akq * 4]);
    pb0 = *reinterpret_cast<const float4*>(&W_p[(size_t)bkk * P_ + bnq * 4]);
    pb1 = *reinterpret_cast<const float4*>(&W_p[(size_t)(bkk + 16) * P_ + bnq * 4]);

    for (int kb = 0; kb < 33; ++kb) {
        // store prefetched tiles
        Ad[akq * 4 + 0][ar] = pack2(pa.x, pa.x);
        Ad[akq * 4 + 1][ar] = pack2(pa.y, pa.y);
        Ad[akq * 4 + 2][ar] = pack2(pa.z, pa.z);
        Ad[akq * 4 + 3][ar] = pack2(pa.w, pa.w);
        *reinterpret_cast<float4*>(&Bsf[bkk][bnq * 4])      = pb0;
        *reinterpret_cast<float4*>(&Bsf[bkk + 16][bnq * 4]) = pb1;
        __syncthreads();

        // prefetch next tile while computing
        if (kb < 32) {
            int kg0 = (kb + 1) * 32;
            int kgf = kg0 + akq * 4;
            if (kgf < FC)
                pa = *reinterpret_cast<const float4*>(&x[(size_t)(row0 + ar) * FC + kgf]);
            else
                pa = *reinterpret_cast<const float4*>(&stat[b * S_ + (kgf - FC)]);
            pb0 = *reinterpret_cast<const float4*>(&W_p[(size_t)(kg0 + bkk) * P_ + bnq * 4]);
            pb1 = *reinterpret_cast<const float4*>(&W_p[(size_t)(kg0 + bkk + 16) * P_ + bnq * 4]);
        }

        #pragma unroll
        for (int kk = 0; kk < 32; ++kk) {
            double a0 = Ad[kk][m0];                       // broadcast
            double a1 = Ad[kk][m0 + 1];
            const double* brow = reinterpret_cast<const double*>(&Bsf[kk][0]);
            double b0 = brow[ng];                         // conflict-free 8B stride
            double b1 = brow[ng + 16];
            fma2(acc0, a0, b0);
            fma2(acc1, a0, b1);
            fma2(acc2, a1, b0);
            fma2(acc3, a1, b1);
        }
        __syncthreads();
    }

    // epilogue: bias + relu -> g_point (float2 stores, lane-contiguous)
    float2 bb0 = *reinterpret_cast<const float2*>(&b_p[2 * ng]);
    float2 bb1 = *reinterpret_cast<const float2*>(&b_p[2 * ng + 32]);
    int r0 = row0 + m0;

    float2 v;
    float2 p;
    p = unpack2(acc0);
    v = make_float2(fmaxf(p.x + bb0.x, 0.f), fmaxf(p.y + bb0.y, 0.f));
    *reinterpret_cast<float2*>(&g_point[(size_t)r0 * P_ + 2 * ng]) = v;
    p = unpack2(acc1);
    v = make_float2(fmaxf(p.x + bb1.x, 0.f), fmaxf(p.y + bb1.y, 0.f));
    *reinterpret_cast<float2*>(&g_point[(size_t)r0 * P_ + 2 * ng + 32]) = v;
    p = unpack2(acc2);
    v = make_float2(fmaxf(p.x + bb0.x, 0.f), fmaxf(p.y + bb0.y, 0.f));
    *reinterpret_cast<float2*>(&g_point[(size_t)(r0 + 1) * P_ + 2 * ng]) = v;
    p = unpack2(acc3);
    v = make_float2(fmaxf(p.x + bb1.x, 0.f), fmaxf(p.y + bb1.y, 0.f));
    *reinterpret_cast<float2*>(&g_point[(size_t)(r0 + 1) * P_ + 2 * ng + 32]) = v;
}

// ============================================================================
// Kernel 2: interleaved roles (UNCHANGED from round 6, measured 53.4us).
// even blocks: conv (b,f) -> out ch16..31.
// odd blocks: stream ch0..15 (relu x) + ch32..95 (g_point bcast).
// ============================================================================
__global__ __launch_bounds__(256)
void tpc_fuse(const float* __restrict__ x,
              const float* __restrict__ conv_w,
              const float* __restrict__ conv_b,
              float* __restrict__ out)
{
    __shared__ __align__(16) float xs[T_ + 6][17];  // 17.8 KB, conflict-free scalar reads
    __shared__ __align__(16) float ws[64][20];      // [c*4+k][co], LDS.128 = packed co-pairs
    __shared__ float bsv[16];

    const int tid = threadIdx.x;

    if ((blockIdx.x & 1) == 0) {
        // ---------------- CONV ROLE ----------------
        const int cb = blockIdx.x >> 1;
        const int b  = cb >> 6;
        const int f  = cb & 63;
        const size_t xrow0 = ((size_t)b * T_ * F_ + f) * C_;

        // x slab (rows 0..5 = zero pad; row r -> t = r-6)
        #pragma unroll
        for (int l = 0; l < 5; ++l) {
            int idx = tid + l * 256;
            if (idx < (T_ + 6) * 4) {
                int r = idx >> 2;
                int q = idx & 3;
                float4 v = make_float4(0.f, 0.f, 0.f, 0.f);
                if (r >= 6)
                    v = *reinterpret_cast<const float4*>(&x[xrow0 + (size_t)(r - 6) * FC + q * 4]);
                xs[r][q * 4 + 0] = v.x;
                xs[r][q * 4 + 1] = v.y;
                xs[r][q * 4 + 2] = v.z;
                xs[r][q * 4 + 3] = v.w;
            }
        }
        // weights transposed to [ck][co]
        {
            int co = tid >> 4;
            int c  = tid & 15;
            float4 w = *reinterpret_cast<const float4*>(&conv_w[((size_t)f * CO_ + co) * 64 + c * 4]);
            ws[c * 4 + 0][co] = w.x;
            ws[c * 4 + 1][co] = w.y;
            ws[c * 4 + 2][co] = w.z;
            ws[c * 4 + 3][co] = w.w;
        }
        if (tid < 16) bsv[tid] = conv_b[f * CO_ + tid];
        __syncthreads();

        const int t0  = (tid >> 2) * 4;
        const int co0 = (tid & 3) * 4;

        double acc[4][2];
        #pragma unroll
        for (int i = 0; i < 4; ++i) { acc[i][0] = 0.0; acc[i][1] = 0.0; }

        #pragma unroll 4
        for (int c = 0; c < C_; ++c) {
            double ad[10];
            #pragma unroll
            for (int r = 0; r < 10; ++r) {
                float a = xs[t0 + r][c];
                ad[r] = pack2(a, a);            // alu-pipe MOV, fma pipe untouched
            }
            #pragma unroll
            for (int k = 0; k < K_; ++k) {
                double2 w = *reinterpret_cast<const double2*>(&ws[c * 4 + k][co0]);
                #pragma unroll
                for (int i = 0; i < 4; ++i) {
                    fma2(acc[i][0], ad[i + 2 * k], w.x);
                    fma2(acc[i][1], ad[i + 2 * k], w.y);
                }
            }
        }

        // bias + relu, store ch16..31 straight from registers
        float4 bb = *reinterpret_cast<const float4*>(&bsv[co0]);
        float* ob = out + ((size_t)b * T_ * F_ + f) * OUTC;
        #pragma unroll
        for (int i = 0; i < 4; ++i) {
            float2 q0 = unpack2(acc[i][0]);
            float2 q1 = unpack2(acc[i][1]);
            float4 v = make_float4(fmaxf(q0.x + bb.x, 0.f), fmaxf(q0.y + bb.y, 0.f),
                                   fmaxf(q1.x + bb.z, 0.f), fmaxf(q1.y + bb.w, 0.f));
            *reinterpret_cast<float4*>(&ob[(size_t)(t0 + i) * RSTR + 16 + co0]) = v;
        }
    } else {
        // ---------------- STREAM ROLE ----------------
        const int rb = blockIdx.x >> 1;
        const int row_base = rb * 4;

        // ch 0..15: relu(x) (1024 float4)
        #pragma unroll
        for (int l = 0; l < 4; ++l) {
            int idx  = tid + l * 256;
            int r    = idx >> 8;
            int rest = idx & 255;            // f*4 + q
            int row  = row_base + r;
            float4 v = *reinterpret_cast<const float4*>(&x[(size_t)row * FC + rest * 4]);
            v.x = fmaxf(v.x, 0.f); v.y = fmaxf(v.y, 0.f);
            v.z = fmaxf(v.z, 0.f); v.w = fmaxf(v.w, 0.f);
            int f = rest >> 2;
            int q = rest & 3;
            *reinterpret_cast<float4*>(&out[(size_t)row * RSTR + f * OUTC + q * 4]) = v;
        }
        // ch 32..95: g_point broadcast (4096 float4)
        const int q  = tid & 15;
        const int f0 = tid >> 4;
        #pragma unroll
        for (int rr = 0; rr < 4; ++rr) {
            int row  = row_base + rr;
            float4 v = *reinterpret_cast<const float4*>(&g_point[(size_t)row * P_ + q * 4]);
            float* ob = out + (size_t)row * RSTR + 32 + q * 4;
            #pragma unroll
            for (int ff = 0; ff < 4; ++ff) {
                int f = ff * 16 + f0;
                *reinterpret_cast<float4*>(&ob[(size_t)f * OUTC]) = v;
            }
        }
    }
}

extern "C" void kernel_launch(void* const* d_in, const int* in_sizes, int n_in,
                              void* d_out, int out_size)
{
    const float* x      = (const float*)d_in[0];   // [32,256,64,16]
    const float* statv  = (const float*)d_in[1];   // [32,32]
    const float* conv_w = (const float*)d_in[2];   // [64,16,16,4]
    const float* conv_b = (const float*)d_in[3];   // [64,16]
    const float* W_p    = (const float*)d_in[4];   // [1056,64]
    const float* b_p    = (const float*)d_in[5];   // [64]
    float* out = (float*)d_out;                    // [32,256,64,96]

    tpc_gemm<<<ROWS / 32, 256>>>(x, statv, W_p, b_p);
    tpc_fuse<<<4096, 256>>>(x, conv_w, conv_b, out);
}